// round 4
// baseline (speedup 1.0000x reference)
#include <cuda_runtime.h>
#include <cstdint>

// MultiScaleDeformableAttention
// value:              (8, 22223, 8, 32)  float32
// sampling_locations: (8, 900, 8, 4, 4, 2) float32
// attention_weights:  (8, 900, 8, 4, 4) float32
// out:                (8, 900, 256) float32
//
// One warp per (b, q, h). lane = channel c (d == 32 == warp size).
// Each bilinear corner load is a coalesced 128B warp-wide gather.
// Out-of-bounds corners: index clamped in-bounds, weight forced to 0
// (branch-free, math identical to the reference's masked gather).

#define NQ 900
#define NH 8
#define ND 32
#define BS 8
#define NKEYS 22223
#define NWARPS (BS * NQ * NH)   // 57600

__global__ __launch_bounds__(256, 8)
void msda_kernel(const float* __restrict__ value,
                 const float* __restrict__ loc,
                 const float* __restrict__ aw,
                 float* __restrict__ out)
{
    const int gwarp = (blockIdx.x * blockDim.x + threadIdx.x) >> 5;
    const int lane  = threadIdx.x & 31;
    if (gwarp >= NWARPS) return;

    const int h = gwarp % NH;
    const int q = (gwarp / NH) % NQ;
    const int b = gwarp / (NH * NQ);

    // loc: (((b*NQ + q)*NH + h)*4*4*2) contiguous 32 floats
    const size_t bqh = (size_t)(b * NQ + q) * NH + h;
    const float* __restrict__ locp = loc + bqh * 32;
    const float* __restrict__ awp  = aw  + bqh * 16;

    // value element (b, key, h, c): ((b*NKEYS + key)*NH + h)*ND + c
    const float* __restrict__ vbase =
        value + ((size_t)b * NKEYS * NH + h) * ND + lane;

    const int LVL_H[4] = {100, 50, 25, 13};
    const int LVL_W[4] = {167, 84, 42, 21};
    const int LVL_S[4] = {0, 16700, 20900, 21950};

    float acc = 0.0f;

    #pragma unroll
    for (int l = 0; l < 4; ++l) {
        const int H = LVL_H[l];
        const int W = LVL_W[l];
        const int S = LVL_S[l];
        #pragma unroll
        for (int p = 0; p < 4; ++p) {
            const int pi = l * 4 + p;
            const float lx = __ldg(&locp[pi * 2 + 0]);
            const float ly = __ldg(&locp[pi * 2 + 1]);
            const float w  = __ldg(&awp[pi]);

            const float x = lx * (float)W - 0.5f;
            const float y = ly * (float)H - 0.5f;
            const float x0f = floorf(x);
            const float y0f = floorf(y);
            const int x0 = (int)x0f;
            const int y0 = (int)y0f;
            const int x1 = x0 + 1;
            const int y1 = y0 + 1;
            const float fx1 = x - x0f;            // frac weights
            const float fy1 = y - y0f;
            const float fx0 = 1.0f - fx1;
            const float fy0 = 1.0f - fy1;

            // validity -> zero out the corresponding weight factor
            const float mx0 = (x0 >= 0 && x0 < W) ? fx0 : 0.0f;
            const float mx1 = (x1 >= 0 && x1 < W) ? fx1 : 0.0f;
            const float my0 = (y0 >= 0 && y0 < H) ? fy0 : 0.0f;
            const float my1 = (y1 >= 0 && y1 < H) ? fy1 : 0.0f;

            // clamped (always in-bounds) indices
            const int cx0 = min(max(x0, 0), W - 1);
            const int cx1 = min(max(x1, 0), W - 1);
            const int cy0 = min(max(y0, 0), H - 1);
            const int cy1 = min(max(y1, 0), H - 1);

            const int r0 = S + cy0 * W;
            const int r1 = S + cy1 * W;

            const float c00 = __ldg(vbase + (size_t)(r0 + cx0) * (NH * ND));
            const float c10 = __ldg(vbase + (size_t)(r0 + cx1) * (NH * ND));
            const float c01 = __ldg(vbase + (size_t)(r1 + cx0) * (NH * ND));
            const float c11 = __ldg(vbase + (size_t)(r1 + cx1) * (NH * ND));

            const float s = c00 * (mx0 * my0) + c10 * (mx1 * my0)
                          + c01 * (mx0 * my1) + c11 * (mx1 * my1);
            acc = fmaf(w, s, acc);
        }
    }

    // out: (b, q, h*ND + c)
    out[bqh * ND + lane] = acc;
}

extern "C" void kernel_launch(void* const* d_in, const int* in_sizes, int n_in,
                              void* d_out, int out_size)
{
    const float* value = (const float*)d_in[0];
    const float* loc   = (const float*)d_in[1];
    const float* aw    = (const float*)d_in[2];
    float* out = (float*)d_out;

    const int threads = 256;
    const int warps_per_block = threads / 32;
    const int blocks = (NWARPS + warps_per_block - 1) / warps_per_block; // 7200
    msda_kernel<<<blocks, threads>>>(value, loc, aw, out);
}

// round 5
// speedup vs baseline: 1.2280x; 1.2280x over previous
#include <cuda_runtime.h>
#include <cstdint>

// MultiScaleDeformableAttention — float4-vectorized gather.
// value:              (8, 22223, 8, 32)  float32
// sampling_locations: (8, 900, 8, 4, 4, 2) float32
// attention_weights:  (8, 900, 8, 4, 4) float32
// out:                (8, 900, 256) float32
//
// 8 threads per (b,q,h) tuple; each thread owns 4 channels (float4).
// Corner gathers are LDG.128; all indexing in 32-bit.
// OOB corners: clamp index in-bounds, zero the bilinear weight factor.

#define NQ 900
#define NH 8
#define ND 32
#define BS 8
#define NKEYS 22223
#define NTUP (BS * NQ * NH)        // 57600 tuples
#define TPT 8                      // threads per tuple (32 channels / 4)

__global__ __launch_bounds__(256)
void msda_kernel(const float* __restrict__ value,
                 const float* __restrict__ loc,
                 const float* __restrict__ aw,
                 float* __restrict__ out)
{
    const int gt = blockIdx.x * blockDim.x + threadIdx.x;
    const int t  = gt >> 3;        // tuple id
    const int c4 = gt & 7;         // channel-group (4 floats)

    // t = (b*NQ + q)*NH + h
    const int h  = t & 7;
    const int bq = t >> 3;
    const int q  = bq % NQ;
    const int b  = bq / NQ;
    (void)q;

    const float* __restrict__ locp = loc + (size_t)t * 32;
    const float* __restrict__ awp  = aw  + (size_t)t * 16;

    // value element (b, key, h, c): ((b*NKEYS + key)*NH + h)*ND + c
    // per-thread base: fold b, h, channel-group; key contributes key*256.
    const float* __restrict__ vbase =
        value + (size_t)b * (NKEYS * NH * ND) + h * ND + c4 * 4;

    const int LVL_H[4] = {100, 50, 25, 13};
    const int LVL_W[4] = {167, 84, 42, 21};
    const int LVL_S[4] = {0, 16700, 20900, 21950};

    float4 acc = make_float4(0.f, 0.f, 0.f, 0.f);

    #pragma unroll
    for (int l = 0; l < 4; ++l) {
        const int H = LVL_H[l];
        const int W = LVL_W[l];
        const int S = LVL_S[l];
        #pragma unroll
        for (int p = 0; p < 4; ++p) {
            const int pi = l * 4 + p;
            const float2 lxy = __ldg((const float2*)locp + pi);
            const float  w   = __ldg(&awp[pi]);

            const float x = lxy.x * (float)W - 0.5f;
            const float y = lxy.y * (float)H - 0.5f;
            const float x0f = floorf(x);
            const float y0f = floorf(y);
            const int x0 = (int)x0f;
            const int y0 = (int)y0f;
            const int x1 = x0 + 1;
            const int y1 = y0 + 1;
            const float fx1 = x - x0f;
            const float fy1 = y - y0f;
            const float fx0 = 1.0f - fx1;
            const float fy0 = 1.0f - fy1;

            // zero weight factor when the corner is out of range
            const float mx0 = (x0 >= 0 && x0 < W) ? fx0 : 0.0f;
            const float mx1 = (x1 >= 0 && x1 < W) ? fx1 : 0.0f;
            const float my0 = (y0 >= 0 && y0 < H) ? fy0 * w : 0.0f;
            const float my1 = (y1 >= 0 && y1 < H) ? fy1 * w : 0.0f;

            // clamped (always in-bounds) indices
            const int cx0 = min(max(x0, 0), W - 1);
            const int cx1 = min(max(x1, 0), W - 1);
            const int cy0 = min(max(y0, 0), H - 1);
            const int cy1 = min(max(y1, 0), H - 1);

            const int r0 = S + cy0 * W;
            const int r1 = S + cy1 * W;

            const float4 v00 = __ldg((const float4*)(vbase + (r0 + cx0) * (NH * ND)));
            const float4 v10 = __ldg((const float4*)(vbase + (r0 + cx1) * (NH * ND)));
            const float4 v01 = __ldg((const float4*)(vbase + (r1 + cx0) * (NH * ND)));
            const float4 v11 = __ldg((const float4*)(vbase + (r1 + cx1) * (NH * ND)));

            const float w00 = mx0 * my0;
            const float w10 = mx1 * my0;
            const float w01 = mx0 * my1;
            const float w11 = mx1 * my1;

            acc.x = fmaf(w00, v00.x, acc.x);
            acc.y = fmaf(w00, v00.y, acc.y);
            acc.z = fmaf(w00, v00.z, acc.z);
            acc.w = fmaf(w00, v00.w, acc.w);

            acc.x = fmaf(w10, v10.x, acc.x);
            acc.y = fmaf(w10, v10.y, acc.y);
            acc.z = fmaf(w10, v10.z, acc.z);
            acc.w = fmaf(w10, v10.w, acc.w);

            acc.x = fmaf(w01, v01.x, acc.x);
            acc.y = fmaf(w01, v01.y, acc.y);
            acc.z = fmaf(w01, v01.z, acc.z);
            acc.w = fmaf(w01, v01.w, acc.w);

            acc.x = fmaf(w11, v11.x, acc.x);
            acc.y = fmaf(w11, v11.y, acc.y);
            acc.z = fmaf(w11, v11.z, acc.z);
            acc.w = fmaf(w11, v11.w, acc.w);
        }
    }

    // out: (b, q, h*ND + c) == tuple-major: out[t*32 + c4*4]
    ((float4*)out)[(size_t)t * 8 + c4] = acc;
}

extern "C" void kernel_launch(void* const* d_in, const int* in_sizes, int n_in,
                              void* d_out, int out_size)
{
    const float* value = (const float*)d_in[0];
    const float* loc   = (const float*)d_in[1];
    const float* aw    = (const float*)d_in[2];
    float* out = (float*)d_out;

    const int total_threads = NTUP * TPT;          // 460800
    const int threads = 256;
    const int blocks = total_threads / threads;    // 1800 (exact)
    msda_kernel<<<blocks, threads>>>(value, loc, aw, out);
}

// round 6
// speedup vs baseline: 1.4416x; 1.1740x over previous
#include <cuda_runtime.h>
#include <cstdint>

// MultiScaleDeformableAttention — float4 gather + depth-2 software pipeline.
// value:              (8, 22223, 8, 32)  float32
// sampling_locations: (8, 900, 8, 4, 4, 2) float32
// attention_weights:  (8, 900, 8, 4, 4) float32
// out:                (8, 900, 256) float32
//
// 8 threads per (b,q,h) tuple; each thread owns 4 channels (float4).
// 16 sampling points processed in a 3-stage rotating pipeline: loads for
// point p+2 are issued while FMAs consume point p -> ~12 LDG.128 in
// flight per warp instead of ~4.

#define NQ 900
#define NH 8
#define ND 32
#define BS 8
#define NKEYS 22223
#define NTUP (BS * NQ * NH)        // 57600 tuples
#define TPT 8                      // threads per tuple (32 channels / 4)
#define VSTRIDE (NH * ND)          // 256 floats per key

__device__ __forceinline__ void point_setup(
    const float* __restrict__ locp, const float* __restrict__ awp,
    int pi, int H, int W, int S,
    int& o00, int& o10, int& o01, int& o11,
    float& w00, float& w10, float& w01, float& w11)
{
    const float2 lxy = __ldg((const float2*)locp + pi);
    const float  w   = __ldg(&awp[pi]);

    const float x = lxy.x * (float)W - 0.5f;
    const float y = lxy.y * (float)H - 0.5f;
    const float x0f = floorf(x);
    const float y0f = floorf(y);
    const int x0 = (int)x0f;
    const int y0 = (int)y0f;
    const int x1 = x0 + 1;
    const int y1 = y0 + 1;
    const float fx1 = x - x0f;
    const float fy1 = y - y0f;
    const float fx0 = 1.0f - fx1;
    const float fy0 = 1.0f - fy1;

    // zero weight factor when the corner is out of range; fold aw in.
    const float mx0 = (x0 >= 0 && x0 < W) ? fx0 : 0.0f;
    const float mx1 = (x1 >= 0 && x1 < W) ? fx1 : 0.0f;
    const float my0 = (y0 >= 0 && y0 < H) ? fy0 * w : 0.0f;
    const float my1 = (y1 >= 0 && y1 < H) ? fy1 * w : 0.0f;

    const int cx0 = min(max(x0, 0), W - 1);
    const int cx1 = min(max(x1, 0), W - 1);
    const int cy0 = min(max(y0, 0), H - 1);
    const int cy1 = min(max(y1, 0), H - 1);

    const int r0 = S + cy0 * W;
    const int r1 = S + cy1 * W;

    o00 = (r0 + cx0) * VSTRIDE;
    o10 = (r0 + cx1) * VSTRIDE;
    o01 = (r1 + cx0) * VSTRIDE;
    o11 = (r1 + cx1) * VSTRIDE;

    w00 = mx0 * my0;
    w10 = mx1 * my0;
    w01 = mx0 * my1;
    w11 = mx1 * my1;
}

__global__ __launch_bounds__(256)
void msda_kernel(const float* __restrict__ value,
                 const float* __restrict__ loc,
                 const float* __restrict__ aw,
                 float* __restrict__ out)
{
    const int gt = blockIdx.x * blockDim.x + threadIdx.x;
    const int t  = gt >> 3;        // tuple id
    const int c4 = gt & 7;         // channel-group (4 floats)

    // t = (b*NQ + q)*NH + h
    const int h  = t & 7;
    const int b  = (t >> 3) / NQ;

    const float* __restrict__ locp = loc + (size_t)t * 32;
    const float* __restrict__ awp  = aw  + (size_t)t * 16;

    const float* __restrict__ vbase =
        value + (size_t)b * (NKEYS * NH * ND) + h * ND + c4 * 4;

    const int LVL_H[4] = {100, 50, 25, 13};
    const int LVL_W[4] = {167, 84, 42, 21};
    const int LVL_S[4] = {0, 16700, 20900, 21950};

    // 3-stage rotating pipeline state (full unroll -> all in registers)
    float4 v00[3], v10[3], v01[3], v11[3];
    float  w00[3], w10[3], w01[3], w11[3];

    // prologue: issue loads for points 0 and 1
    #pragma unroll
    for (int pi = 0; pi < 2; ++pi) {
        const int l = pi >> 2;
        int o00, o10, o01, o11;
        point_setup(locp, awp, pi, LVL_H[l], LVL_W[l], LVL_S[l],
                    o00, o10, o01, o11,
                    w00[pi], w10[pi], w01[pi], w11[pi]);
        v00[pi] = __ldg((const float4*)(vbase + o00));
        v10[pi] = __ldg((const float4*)(vbase + o10));
        v01[pi] = __ldg((const float4*)(vbase + o01));
        v11[pi] = __ldg((const float4*)(vbase + o11));
    }

    float4 acc0 = make_float4(0.f, 0.f, 0.f, 0.f);
    float4 acc1 = make_float4(0.f, 0.f, 0.f, 0.f);

    #pragma unroll
    for (int pi = 0; pi < 16; ++pi) {
        const int cur = pi % 3;
        // issue loads for point pi+2 before consuming point pi
        if (pi < 14) {
            const int nxt = (pi + 2) % 3;
            const int pn  = pi + 2;
            const int l   = pn >> 2;
            int o00, o10, o01, o11;
            point_setup(locp, awp, pn, LVL_H[l], LVL_W[l], LVL_S[l],
                        o00, o10, o01, o11,
                        w00[nxt], w10[nxt], w01[nxt], w11[nxt]);
            v00[nxt] = __ldg((const float4*)(vbase + o00));
            v10[nxt] = __ldg((const float4*)(vbase + o10));
            v01[nxt] = __ldg((const float4*)(vbase + o01));
            v11[nxt] = __ldg((const float4*)(vbase + o11));
        }

        float4& acc = (pi & 1) ? acc1 : acc0;
        const float a = w00[cur], bw = w10[cur], c = w01[cur], d = w11[cur];
        const float4 p00 = v00[cur], p10 = v10[cur], p01 = v01[cur], p11 = v11[cur];

        acc.x = fmaf(a, p00.x, acc.x);
        acc.y = fmaf(a, p00.y, acc.y);
        acc.z = fmaf(a, p00.z, acc.z);
        acc.w = fmaf(a, p00.w, acc.w);

        acc.x = fmaf(bw, p10.x, acc.x);
        acc.y = fmaf(bw, p10.y, acc.y);
        acc.z = fmaf(bw, p10.z, acc.z);
        acc.w = fmaf(bw, p10.w, acc.w);

        acc.x = fmaf(c, p01.x, acc.x);
        acc.y = fmaf(c, p01.y, acc.y);
        acc.z = fmaf(c, p01.z, acc.z);
        acc.w = fmaf(c, p01.w, acc.w);

        acc.x = fmaf(d, p11.x, acc.x);
        acc.y = fmaf(d, p11.y, acc.y);
        acc.z = fmaf(d, p11.z, acc.z);
        acc.w = fmaf(d, p11.w, acc.w);
    }

    float4 r;
    r.x = acc0.x + acc1.x;
    r.y = acc0.y + acc1.y;
    r.z = acc0.z + acc1.z;
    r.w = acc0.w + acc1.w;

    // out: tuple-major float4: out[t*8 + c4]
    ((float4*)out)[(size_t)t * 8 + c4] = r;
}

extern "C" void kernel_launch(void* const* d_in, const int* in_sizes, int n_in,
                              void* d_out, int out_size)
{
    const float* value = (const float*)d_in[0];
    const float* loc   = (const float*)d_in[1];
    const float* aw    = (const float*)d_in[2];
    float* out = (float*)d_out;

    const int total_threads = NTUP * TPT;          // 460800
    const int threads = 256;
    const int blocks = total_threads / threads;    // 1800 (exact)
    msda_kernel<<<blocks, threads>>>(value, loc, aw, out);
}